// round 17
// baseline (speedup 1.0000x reference)
#include <cuda_runtime.h>
#include <cuda_fp16.h>
#include <cstdint>
#include <stdint.h>
#include <math.h>

// Problem constants (fixed by the dataset)
#define N_NODES 100000
#define N_EDGES 1600000
#define DIM 128
#define ODIM 64
#define WSLOT 16384
#define WTOT (5 * WSLOT + ODIM * DIM)
#define PADB 272   // smem row stride in bytes; 68 words -> conflict-free LDSM
#define SCHUNK 1024

// ---------------- scratch (static device globals; no allocation) -----------
__device__ unsigned char g_M8[(size_t)N_NODES * DIM]; // fp8-e4m3 messages (pre-scaled by dinv_src)
__device__ __half       g_H16[(size_t)N_NODES * DIM]; // fp16 aggregated features
__device__ int          g_deg[N_NODES];
__device__ int          g_cur[N_NODES];
__device__ int          g_off[N_NODES + 1];
__device__ int          g_csr[N_EDGES];
__device__ int          g_bsum[128];
__device__ float        g_dinv[N_NODES];
__device__ __half       g_Wf[WTOT];                   // fp16 transposed weights [N][K]

// ---------------- PTX helpers (all baseline ISA, valid at compute_100) -----
__device__ __forceinline__ unsigned int smem_u32(const void* p) {
    unsigned int a;
    asm("{ .reg .u64 t; cvta.to.shared.u64 t, %1; cvt.u32.u64 %0, t; }" : "=r"(a) : "l"(p));
    return a;
}
__device__ __forceinline__ void mma_f16(float* c, const unsigned int* a,
                                        const unsigned int* b) {
    asm volatile(
        "mma.sync.aligned.m16n8k16.row.col.f32.f16.f16.f32 "
        "{%0,%1,%2,%3}, {%4,%5,%6,%7}, {%8,%9}, {%0,%1,%2,%3};"
        : "+f"(c[0]), "+f"(c[1]), "+f"(c[2]), "+f"(c[3])
        : "r"(a[0]), "r"(a[1]), "r"(a[2]), "r"(a[3]), "r"(b[0]), "r"(b[1]));
}
__device__ __forceinline__ void ldsm_x4(unsigned int* r, unsigned int addr) {
    asm volatile("ldmatrix.sync.aligned.m8n8.x4.shared.b16 {%0,%1,%2,%3}, [%4];"
                 : "=r"(r[0]), "=r"(r[1]), "=r"(r[2]), "=r"(r[3]) : "r"(addr));
}
__device__ __forceinline__ unsigned short f32x2_to_e4m3x2(float hi, float lo) {
    unsigned short us;
    asm("cvt.rn.satfinite.e4m3x2.f32 %0, %1, %2;" : "=h"(us) : "f"(hi), "f"(lo));
    return us;   // byte0 = lo, byte1 = hi
}
__device__ __forceinline__ __half2 e4m3x2_to_h2(unsigned short w) {
    unsigned int r;
    asm("cvt.rn.f16x2.e4m3x2 %0, %1;" : "=r"(r) : "h"(w));
    return *(__half2*)&r;
}

// ---------------- setup kernels --------------------------------------------
__global__ void k_count(const int* __restrict__ dst, int e) {
    int i = blockIdx.x * blockDim.x + threadIdx.x;
    if (i < e) atomicAdd(&g_deg[dst[i]], 1);
}
__global__ void k_bsum(int n) {            // block sums + dinv (deg final here)
    __shared__ int sh[SCHUNK];
    int i = blockIdx.x * SCHUNK + threadIdx.x;
    int d = (i < n) ? g_deg[i] : 0;
    if (i < n) g_dinv[i] = rsqrtf((float)(d + 1));
    sh[threadIdx.x] = d;
    __syncthreads();
    for (int off = SCHUNK / 2; off > 0; off >>= 1) {
        if (threadIdx.x < off) sh[threadIdx.x] += sh[threadIdx.x + off];
        __syncthreads();
    }
    if (threadIdx.x == 0) g_bsum[blockIdx.x] = sh[0];
}
__global__ void k_bscan(int nb) {
    __shared__ int sh[128];
    int v = (threadIdx.x < nb) ? g_bsum[threadIdx.x] : 0;
    sh[threadIdx.x] = v;
    __syncthreads();
    for (int off = 1; off < 128; off <<= 1) {
        int t = (threadIdx.x >= off) ? sh[threadIdx.x - off] : 0;
        __syncthreads();
        sh[threadIdx.x] += t;
        __syncthreads();
    }
    if (threadIdx.x < nb) g_bsum[threadIdx.x] = sh[threadIdx.x] - v;
}
__global__ void k_offsets(int n) {
    __shared__ int sh[SCHUNK];
    int i = blockIdx.x * SCHUNK + threadIdx.x;
    int v = (i < n) ? g_deg[i] : 0;
    sh[threadIdx.x] = v;
    __syncthreads();
    for (int off = 1; off < SCHUNK; off <<= 1) {
        int t = (threadIdx.x >= off) ? sh[threadIdx.x - off] : 0;
        __syncthreads();
        sh[threadIdx.x] += t;
        __syncthreads();
    }
    int excl = g_bsum[blockIdx.x] + sh[threadIdx.x] - v;
    if (i < n) { g_off[i] = excl; g_cur[i] = excl; }   // cur preloaded as cursor
    if (i == n - 1) g_off[n] = excl + v;
}
__global__ void k_fill(const int* __restrict__ src, const int* __restrict__ dst, int e) {
    int i = blockIdx.x * blockDim.x + threadIdx.x;
    if (i < e) {
        int pos = atomicAdd(&g_cur[dst[i]], 1);
        g_csr[pos] = src[i];
    }
}
__global__ void k_convW_all(const float* __restrict__ W0, const float* __restrict__ W1,
                            const float* __restrict__ W2, const float* __restrict__ W3,
                            const float* __restrict__ Wm1, const float* __restrict__ Wm2) {
    int i = blockIdx.x * blockDim.x + threadIdx.x;
    if (i >= WTOT) return;
    int slot = i >> 14;
    int j = i & 16383;
    const float* W;
    int N;
    switch (slot) {
        case 0:  W = W0;  N = 128; break;
        case 1:  W = W1;  N = 128; break;
        case 2:  W = W2;  N = 128; break;
        case 3:  W = W3;  N = 128; break;
        case 4:  W = Wm1; N = 128; break;
        default: W = Wm2; N = 64;  break;
    }
    const int K = 128;
    int nrow = j / K;
    int k = j % K;
    g_Wf[i] = __float2half_rn(W[k * N + nrow]);
}

// ---------------- GCN-layer GEMM (ldmatrix fragments) ----------------------
// acc = act(A) @ W; act = relu(a+abias) if abias (A16 or A32 input).
// Epilogue: C8[row] = e4m3(acc * dinv[row])
__global__ void __launch_bounds__(256, 2)
k_gemm128(const float* __restrict__ A32, const __half* __restrict__ A16,
          const float* __restrict__ abias, const __half* __restrict__ Wf,
          unsigned char* __restrict__ C8, int n)
{
    extern __shared__ __align__(16) char smem[];
    const unsigned int A_OF = 0;
    const unsigned int B_OF = 128 * PADB;
    const int tid  = threadIdx.x;
    const int wid  = tid >> 5;
    const int lane = tid & 31;
    const int wr   = wid >> 1;
    const int wc   = wid & 1;
    const int row0 = blockIdx.x * 128;

    // ---- A tile -> fp16 smem, fused relu(+abias)
    for (int i = tid; i < 128 * 16; i += 256) {
        int row = i >> 4;
        int unit = i & 15;
        int grow = row0 + row;
        uint4 u = make_uint4(0, 0, 0, 0);
        __half2* hp = (__half2*)&u;
        if (grow < n) {
            if (A16) {
                u = *(const uint4*)(A16 + (size_t)grow * 128 + unit * 8);
            } else {
                const float4* p = (const float4*)(A32 + (size_t)grow * 128 + unit * 8);
                float4 a0 = p[0], a1 = p[1];
                hp[0] = __floats2half2_rn(a0.x, a0.y);
                hp[1] = __floats2half2_rn(a0.z, a0.w);
                hp[2] = __floats2half2_rn(a1.x, a1.y);
                hp[3] = __floats2half2_rn(a1.z, a1.w);
            }
        }
        if (abias) {
            const float4* b = (const float4*)(abias + unit * 8);
            float4 b0 = b[0], b1 = b[1];
            float bb[8];
            bb[0] = b0.x; bb[1] = b0.y; bb[2] = b0.z; bb[3] = b0.w;
            bb[4] = b1.x; bb[5] = b1.y; bb[6] = b1.z; bb[7] = b1.w;
#pragma unroll
            for (int j = 0; j < 4; j++) {
                float2 f = __half22float2(hp[j]);
                f.x = fmaxf(f.x + bb[2 * j], 0.f);
                f.y = fmaxf(f.y + bb[2 * j + 1], 0.f);
                hp[j] = __floats2half2_rn(f.x, f.y);
            }
        }
        *(uint4*)(smem + A_OF + (unsigned int)row * PADB + (unsigned int)unit * 16) = u;
    }
    // ---- W tile (128 rows)
    for (int i = tid; i < 128 * 16; i += 256) {
        int row = i >> 4;
        int unit = i & 15;
        *(uint4*)(smem + B_OF + (unsigned int)row * PADB + (unsigned int)unit * 16) =
            ((const uint4*)Wf)[row * 16 + unit];
    }
    __syncthreads();

    const unsigned int sb = smem_u32(smem);
    // ldmatrix lane addressing
    unsigned int aAddr[2], bAddr[4];
#pragma unroll
    for (int mt = 0; mt < 2; mt++)
        aAddr[mt] = sb + A_OF +
                    (unsigned int)(wr * 32 + mt * 16 + (lane & 15)) * PADB +
                    (unsigned int)((lane >> 4) << 4);
#pragma unroll
    for (int p = 0; p < 4; p++)
        bAddr[p] = sb + B_OF +
                   (unsigned int)(wc * 64 + p * 16 + (lane & 7) + ((lane >> 4) << 3)) * PADB +
                   (unsigned int)(((lane >> 3) & 1) << 4);

    float acc[2][8][4];
#pragma unroll
    for (int mt = 0; mt < 2; mt++)
#pragma unroll
        for (int nt = 0; nt < 8; nt++)
#pragma unroll
            for (int j = 0; j < 4; j++) acc[mt][nt][j] = 0.f;

#pragma unroll
    for (int ks = 0; ks < 8; ks++) {
        const unsigned int ko = (unsigned int)ks * 32;
        unsigned int a0v[4], a1v[4];
        ldsm_x4(a0v, aAddr[0] + ko);
        ldsm_x4(a1v, aAddr[1] + ko);
#pragma unroll
        for (int p = 0; p < 4; p++) {
            unsigned int bq[4];
            ldsm_x4(bq, bAddr[p] + ko);
            mma_f16(acc[0][2 * p],     a0v, bq);
            mma_f16(acc[0][2 * p + 1], a0v, bq + 2);
            mma_f16(acc[1][2 * p],     a1v, bq);
            mma_f16(acc[1][2 * p + 1], a1v, bq + 2);
        }
    }

    // ---- scale-free fp8 epilogue: store e4m3(acc * dinv[row])
    const int g  = lane >> 2;
    const int tg = lane & 3;
#pragma unroll
    for (int mt = 0; mt < 2; mt++) {
        int lr = wr * 32 + mt * 16 + g;
        int grow = row0 + lr;
        float d0 = (grow < n) ? g_dinv[grow] : 0.f;
        float d1 = (grow + 8 < n) ? g_dinv[grow + 8] : 0.f;
#pragma unroll
        for (int nt = 0; nt < 8; nt++) {
            int col = wc * 64 + nt * 8 + tg * 2;
            if (grow < n)
                *(unsigned short*)(C8 + (size_t)grow * 128 + col) =
                    f32x2_to_e4m3x2(acc[mt][nt][1] * d0, acc[mt][nt][0] * d0);
            if (grow + 8 < n)
                *(unsigned short*)(C8 + (size_t)(grow + 8) * 128 + col) =
                    f32x2_to_e4m3x2(acc[mt][nt][3] * d1, acc[mt][nt][2] * d1);
        }
    }
}

// ---------------- fused MLP: relu(H+b3)@Wm1+bm1 -> @Wm2+bm2 -> log_softmax --
__global__ void __launch_bounds__(256, 2)
k_mlp(const __half* __restrict__ A16, const float* __restrict__ b3,
      const __half* __restrict__ Wm1f, const float* __restrict__ bm1,
      const __half* __restrict__ Wm2f, const float* __restrict__ bm2,
      float* __restrict__ osm, int n)
{
    extern __shared__ __align__(16) char smem[];
    const unsigned int A_OF = 0;
    const unsigned int B_OF = 128 * PADB;
    const int tid  = threadIdx.x;
    const int wid  = tid >> 5;
    const int lane = tid & 31;
    const int wr   = wid >> 1;
    const int wc   = wid & 1;
    const int row0 = blockIdx.x * 128;
    const int g  = lane >> 2;
    const int tg = lane & 3;

    // ---- A = relu(H16 + b3) tile; B = Wm1 tile
    for (int i = tid; i < 128 * 16; i += 256) {
        int row = i >> 4;
        int unit = i & 15;
        int grow = row0 + row;
        uint4 u = make_uint4(0, 0, 0, 0);
        __half2* hp = (__half2*)&u;
        if (grow < n) u = *(const uint4*)(A16 + (size_t)grow * 128 + unit * 8);
        const float4* b = (const float4*)(b3 + unit * 8);
        float4 b0 = b[0], b1 = b[1];
        float bb[8];
        bb[0] = b0.x; bb[1] = b0.y; bb[2] = b0.z; bb[3] = b0.w;
        bb[4] = b1.x; bb[5] = b1.y; bb[6] = b1.z; bb[7] = b1.w;
#pragma unroll
        for (int j = 0; j < 4; j++) {
            float2 f = __half22float2(hp[j]);
            f.x = fmaxf(f.x + bb[2 * j], 0.f);
            f.y = fmaxf(f.y + bb[2 * j + 1], 0.f);
            hp[j] = __floats2half2_rn(f.x, f.y);
        }
        *(uint4*)(smem + A_OF + (unsigned int)row * PADB + (unsigned int)unit * 16) = u;
    }
    for (int i = tid; i < 128 * 16; i += 256) {
        int row = i >> 4;
        int unit = i & 15;
        *(uint4*)(smem + B_OF + (unsigned int)row * PADB + (unsigned int)unit * 16) =
            ((const uint4*)Wm1f)[row * 16 + unit];
    }
    __syncthreads();

    const unsigned int sb = smem_u32(smem);
    unsigned int aAddr[2], bAddr[4];
#pragma unroll
    for (int mt = 0; mt < 2; mt++)
        aAddr[mt] = sb + A_OF +
                    (unsigned int)(wr * 32 + mt * 16 + (lane & 15)) * PADB +
                    (unsigned int)((lane >> 4) << 4);
#pragma unroll
    for (int p = 0; p < 4; p++)
        bAddr[p] = sb + B_OF +
                   (unsigned int)(wc * 64 + p * 16 + (lane & 7) + ((lane >> 4) << 3)) * PADB +
                   (unsigned int)(((lane >> 3) & 1) << 4);

    // ---- MMA 1: T = A @ Wm1 (128 cols)
    float acc[2][8][4];
#pragma unroll
    for (int mt = 0; mt < 2; mt++)
#pragma unroll
        for (int nt = 0; nt < 8; nt++)
#pragma unroll
            for (int j = 0; j < 4; j++) acc[mt][nt][j] = 0.f;

#pragma unroll
    for (int ks = 0; ks < 8; ks++) {
        const unsigned int ko = (unsigned int)ks * 32;
        unsigned int a0v[4], a1v[4];
        ldsm_x4(a0v, aAddr[0] + ko);
        ldsm_x4(a1v, aAddr[1] + ko);
#pragma unroll
        for (int p = 0; p < 4; p++) {
            unsigned int bq[4];
            ldsm_x4(bq, bAddr[p] + ko);
            mma_f16(acc[0][2 * p],     a0v, bq);
            mma_f16(acc[0][2 * p + 1], a0v, bq + 2);
            mma_f16(acc[1][2 * p],     a1v, bq);
            mma_f16(acc[1][2 * p + 1], a1v, bq + 2);
        }
    }

    __syncthreads();   // all MMA1 reads of A and B complete

    // ---- write T (=acc+bm1, fp16) into A area; load Wm2 into B area
#pragma unroll
    for (int mt = 0; mt < 2; mt++) {
        int lr = wr * 32 + mt * 16 + g;
#pragma unroll
        for (int nt = 0; nt < 8; nt++) {
            int col = wc * 64 + nt * 8 + tg * 2;
            float b0 = bm1[col], b1 = bm1[col + 1];
            *(__half2*)(smem + A_OF + (unsigned int)lr * PADB + col * 2) =
                __floats2half2_rn(acc[mt][nt][0] + b0, acc[mt][nt][1] + b1);
            *(__half2*)(smem + A_OF + (unsigned int)(lr + 8) * PADB + col * 2) =
                __floats2half2_rn(acc[mt][nt][2] + b0, acc[mt][nt][3] + b1);
        }
    }
    for (int i = tid; i < 64 * 16; i += 256) {
        int row = i >> 4;
        int unit = i & 15;
        *(uint4*)(smem + B_OF + (unsigned int)row * PADB + (unsigned int)unit * 16) =
            ((const uint4*)Wm2f)[row * 16 + unit];
    }
    __syncthreads();

    // ---- MMA 2: C = T @ Wm2 (64 cols)
    unsigned int b2Addr[2];
#pragma unroll
    for (int p = 0; p < 2; p++)
        b2Addr[p] = sb + B_OF +
                    (unsigned int)(wc * 32 + p * 16 + (lane & 7) + ((lane >> 4) << 3)) * PADB +
                    (unsigned int)(((lane >> 3) & 1) << 4);
#pragma unroll
    for (int mt = 0; mt < 2; mt++)
#pragma unroll
        for (int nt = 0; nt < 4; nt++)
#pragma unroll
            for (int j = 0; j < 4; j++) acc[mt][nt][j] = 0.f;

#pragma unroll
    for (int ks = 0; ks < 8; ks++) {
        const unsigned int ko = (unsigned int)ks * 32;
        unsigned int a0v[4], a1v[4];
        ldsm_x4(a0v, aAddr[0] + ko);
        ldsm_x4(a1v, aAddr[1] + ko);
#pragma unroll
        for (int p = 0; p < 2; p++) {
            unsigned int bq[4];
            ldsm_x4(bq, b2Addr[p] + ko);
            mma_f16(acc[0][2 * p],     a0v, bq);
            mma_f16(acc[0][2 * p + 1], a0v, bq + 2);
            mma_f16(acc[1][2 * p],     a1v, bq);
            mma_f16(acc[1][2 * p + 1], a1v, bq + 2);
        }
    }

    __syncthreads();   // all MMA2 reads of T complete

    // ---- fused log_softmax (sx reuses A area: 128 rows x 68 floats)
    float* sx = (float*)smem;
#pragma unroll
    for (int mt = 0; mt < 2; mt++) {
        int lr = wr * 32 + mt * 16 + g;
#pragma unroll
        for (int nt = 0; nt < 4; nt++) {
            int col = wc * 32 + nt * 8 + tg * 2;
            float b0 = bm2[col], b1 = bm2[col + 1];
            *(float2*)(sx + lr * 68 + col) =
                make_float2(acc[mt][nt][0] + b0, acc[mt][nt][1] + b1);
            *(float2*)(sx + (lr + 8) * 68 + col) =
                make_float2(acc[mt][nt][2] + b0, acc[mt][nt][3] + b1);
        }
    }
    __syncthreads();
    for (int r = wid * 16; r < wid * 16 + 16; r++) {
        int grow = row0 + r;
        if (grow >= n) break;
        float v0 = sx[r * 68 + lane];
        float v1 = sx[r * 68 + lane + 32];
        float m = fmaxf(v0, v1);
#pragma unroll
        for (int o = 16; o > 0; o >>= 1)
            m = fmaxf(m, __shfl_xor_sync(0xFFFFFFFFu, m, o));
        float s = expf(v0 - m) + expf(v1 - m);
#pragma unroll
        for (int o = 16; o > 0; o >>= 1)
            s += __shfl_xor_sync(0xFFFFFFFFu, s, o);
        float lg = m + logf(s);
        osm[(size_t)grow * 64 + lane]      = v0 - lg;
        osm[(size_t)grow * 64 + lane + 32] = v1 - lg;
    }
}

// ---------------- CSR pull-gather (scale-free fp8 rows) --------------------
// H16[d] = half( dinv[d] * sum_{s in N(d) U {d}} M8[s] )   (M8 pre-scaled)
__device__ __forceinline__ void addq8(__half2* a, uint2 u) {
    a[0] = __hadd2(a[0], e4m3x2_to_h2((unsigned short)(u.x)));
    a[1] = __hadd2(a[1], e4m3x2_to_h2((unsigned short)(u.x >> 16)));
    a[2] = __hadd2(a[2], e4m3x2_to_h2((unsigned short)(u.y)));
    a[3] = __hadd2(a[3], e4m3x2_to_h2((unsigned short)(u.y >> 16)));
}

__launch_bounds__(256)
__global__ void k_gather(const uint2* __restrict__ M8,   // row = 16 uint2
                         uint4* __restrict__ H16, int n)  // row = 16 uint4
{
    int warp = (blockIdx.x * blockDim.x + threadIdx.x) >> 5;
    int lane = threadIdx.x & 31;
    if (warp >= n) return;
    int half = lane >> 4;
    int sub  = lane & 15;
    int beg = g_off[warp];
    int total = g_off[warp + 1] - beg + 1;   // +1 self loop (virtual idx 0)

    __half2 acc[4];
#pragma unroll
    for (int k = 0; k < 4; k++) acc[k] = __half2half2(__ushort_as_half(0));

    for (int base = 0; base < total; base += 32) {
        int cnt = total - base;
        if (cnt > 32) cnt = 32;
        int vj = base + lane;
        int idx = 0;
        if (lane < cnt) idx = (vj == 0) ? warp : g_csr[beg + vj - 1];
        int j = 0;
        for (; j + 8 <= cnt; j += 8) {
            int s0 = __shfl_sync(0xFFFFFFFFu, idx, j + half);
            int s1 = __shfl_sync(0xFFFFFFFFu, idx, j + 2 + half);
            int s2 = __shfl_sync(0xFFFFFFFFu, idx, j + 4 + half);
            int s3 = __shfl_sync(0xFFFFFFFFu, idx, j + 6 + half);
            uint2 u0 = M8[(size_t)s0 * 16 + sub];
            uint2 u1 = M8[(size_t)s1 * 16 + sub];
            uint2 u2 = M8[(size_t)s2 * 16 + sub];
            uint2 u3 = M8[(size_t)s3 * 16 + sub];
            addq8(acc, u0);
            addq8(acc, u1);
            addq8(acc, u2);
            addq8(acc, u3);
        }
        if (j + 4 <= cnt) {
            int s0 = __shfl_sync(0xFFFFFFFFu, idx, j + half);
            int s1 = __shfl_sync(0xFFFFFFFFu, idx, j + 2 + half);
            uint2 u0 = M8[(size_t)s0 * 16 + sub];
            uint2 u1 = M8[(size_t)s1 * 16 + sub];
            addq8(acc, u0);
            addq8(acc, u1);
            j += 4;
        }
        if (j + 2 <= cnt) {
            int s = __shfl_sync(0xFFFFFFFFu, idx, j + half);
            uint2 u = M8[(size_t)s * 16 + sub];
            addq8(acc, u);
            j += 2;
        }
        if (j < cnt) {
            int s = __shfl_sync(0xFFFFFFFFu, idx, j);
            if (half == 0) {
                uint2 u = M8[(size_t)s * 16 + sub];
                addq8(acc, u);
            }
        }
    }

    float fa[8];
#pragma unroll
    for (int k = 0; k < 4; k++) {
        float2 t = __half22float2(acc[k]);
        fa[2 * k] = t.x;
        fa[2 * k + 1] = t.y;
    }
#pragma unroll
    for (int k = 0; k < 8; k++)
        fa[k] += __shfl_down_sync(0xFFFFFFFFu, fa[k], 16);

    if (half == 0) {
        float di = g_dinv[warp];
        uint4 o;
        __half2* oh = (__half2*)&o;
#pragma unroll
        for (int i = 0; i < 4; i++)
            oh[i] = __floats2half2_rn(fa[2 * i] * di, fa[2 * i + 1] * di);
        H16[(size_t)warp * 16 + sub] = o;
    }
}

// ---------------- host launcher ---------------------------------------------
extern "C" void kernel_launch(void* const* d_in, const int* in_sizes, int n_in,
                              void* d_out, int out_size)
{
    const float* x   = (const float*)d_in[0];
    const int*   ei  = (const int*)d_in[1];
    const float* W0  = (const float*)d_in[2];
    const float* b0  = (const float*)d_in[3];
    const float* W1  = (const float*)d_in[4];
    const float* b1  = (const float*)d_in[5];
    const float* W2  = (const float*)d_in[6];
    const float* b2  = (const float*)d_in[7];
    const float* W3  = (const float*)d_in[8];
    const float* b3  = (const float*)d_in[9];
    const float* Wm1 = (const float*)d_in[10];
    const float* bm1 = (const float*)d_in[11];
    const float* Wm2 = (const float*)d_in[12];
    const float* bm2 = (const float*)d_in[13];
    float* out = (float*)d_out;

    const int n = in_sizes[0] / DIM;      // 100000
    const int e = in_sizes[1] / 2;        // 1600000
    const int* src = ei;
    const int* dst = ei + e;

    unsigned char* M8 = 0;
    __half* H16 = 0;
    __half* Wf = 0;
    int* Deg = 0;
    cudaGetSymbolAddress((void**)&M8,  g_M8);
    cudaGetSymbolAddress((void**)&H16, g_H16);
    cudaGetSymbolAddress((void**)&Wf,  g_Wf);
    cudaGetSymbolAddress((void**)&Deg, g_deg);

    const int SM128 = 128 * PADB + 128 * PADB;   // 69632
    cudaFuncSetAttribute(k_gemm128, cudaFuncAttributeMaxDynamicSharedMemorySize, SM128);
    cudaFuncSetAttribute(k_mlp,     cudaFuncAttributeMaxDynamicSharedMemorySize, SM128);

    // side stream + fork/join events (created once on the first — correctness —
    // call, outside graph capture; capture records only the event edges)
    static cudaStream_t s2 = 0;
    static cudaEvent_t evF = 0, evD = 0, evB = 0;
    if (!s2) {
        cudaStreamCreateWithFlags(&s2, cudaStreamNonBlocking);
        cudaEventCreateWithFlags(&evF, cudaEventDisableTiming);
        cudaEventCreateWithFlags(&evD, cudaEventDisableTiming);
        cudaEventCreateWithFlags(&evB, cudaEventDisableTiming);
    }

    const int nscanb = (n + SCHUNK - 1) / SCHUNK;
    const int gblocks = (n + 127) / 128;                 // 782
    const int gatherb = (n * 32 + 255) / 256;            // 12500

    // ---- fork: side branch gets weight convert (independent) ----
    cudaEventRecord(evF, 0);
    cudaStreamWaitEvent(s2, evF, 0);
    k_convW_all<<<(WTOT + 255) / 256, 256, 0, s2>>>(W0, W1, W2, W3, Wm1, Wm2);

    // ---- main branch: degrees -> dinv ----
    cudaMemsetAsync(Deg, 0, n * sizeof(int), 0);
    k_count<<<(e + 255) / 256, 256>>>(dst, e);
    k_bsum<<<nscanb, SCHUNK>>>(n);           // also computes dinv
    cudaEventRecord(evD, 0);

    // side branch: layer-0 GEMM (needs Wf slot 0 + dinv + x only)
    cudaStreamWaitEvent(s2, evD, 0);
    k_gemm128<<<gblocks, 256, SM128, s2>>>(x, 0, 0, Wf + 0 * WSLOT, M8, n);
    cudaEventRecord(evB, s2);

    // main branch: CSR build (overlaps with gemm0 on s2)
    k_bscan<<<1, 128>>>(nscanb);
    k_offsets<<<nscanb, SCHUNK>>>(n);        // also preloads g_cur = g_off
    k_fill<<<(e + 255) / 256, 256>>>(src, dst, e);

    // ---- join: gather0 needs CSR (main) + messages (s2) ----
    cudaStreamWaitEvent(0, evB, 0);
    k_gather<<<gatherb, 256>>>((const uint2*)M8, (uint4*)H16, n);

    // ---- layers 1-3 ----
    k_gemm128<<<gblocks, 256, SM128>>>(0, H16, b0, Wf + 1 * WSLOT, M8, n);
    k_gather<<<gatherb, 256>>>((const uint2*)M8, (uint4*)H16, n);

    k_gemm128<<<gblocks, 256, SM128>>>(0, H16, b1, Wf + 2 * WSLOT, M8, n);
    k_gather<<<gatherb, 256>>>((const uint2*)M8, (uint4*)H16, n);

    k_gemm128<<<gblocks, 256, SM128>>>(0, H16, b2, Wf + 3 * WSLOT, M8, n);
    k_gather<<<gatherb, 256>>>((const uint2*)M8, (uint4*)H16, n);

    // ---- fused MLP1 + MLP2 + log_softmax -> out ----
    k_mlp<<<gblocks, 256, SM128>>>(H16, b3, Wf + 4 * WSLOT, bm1,
                                   Wf + 5 * WSLOT, bm2, out, n);
}